// round 15
// baseline (speedup 1.0000x reference)
#include <cuda_runtime.h>
#include <cuda_bf16.h>

// GraphTrainNN: out[b] = prod_g  w2[g] * (w1[g]^2 + w0[g]*x[b,g]^2) / (w1[g]^2 + x[b,g]^2)
// B = 524288 rows, G = 127 genes. x: (B,G) fp32, w: (G,3) fp32.
//
// R15 = R14 (single-wave persistent grid, aligned float4 streaming, low/high
// split-product fold, 48 regs) with 192-THREAD BLOCKS:
//  - at 48 regs the RF admits 42 warps/SM; 256-thread blocks quantize to
//    5x8 = 40 warps, 192-thread blocks hit 7x6 = 42 warps exactly.
//  - grid 1036 = 148 SMs x 7 resident blocks: still exactly one wave.
//  - 4-row group = 508 floats = 127 float4; warp loads slots lane+32j ->
//    4 aligned LDG.128, 512B contiguous per request (minimum sectors).
//  - gene of element (slot,c) = (4*lane + j + c) mod 127 [128 == 1 mod 127]
//    -> 7 fixed (w0, w1^2) pairs per lane.
//  - lane 31 handles row straddles via split points s={3,2,1,0}; others s=4.
//  - 1 fast division per row, 5-level butterfly with 4 interleaved chains,
//    float4 output store. prod(w2) hoisted per warp.

#define GG 127
#define NTHREADS 192
#define NBLOCKS (148 * 7)   // 1036: exactly one wave at 7 blocks/SM

__global__ __launch_bounds__(NTHREADS, 7)
void hill_f4w7_kernel(const float* __restrict__ x,
                      const float* __restrict__ w,
                      float* __restrict__ out,
                      int ngroups)
{
    const int lane   = threadIdx.x & 31;
    const int warp   = (blockIdx.x * blockDim.x + threadIdx.x) >> 5;
    const int nwarps = (gridDim.x * blockDim.x) >> 5;
    const bool l31   = (lane == 31);

    // ---- per-lane params: genes (4*lane + k) mod 127, k = 0..6 ----
    float p0[7], pn[7];
#pragma unroll
    for (int k = 0; k < 7; ++k) {
        int gene = 4 * lane + k;
        if (gene >= GG) gene -= GG;
        p0[k] = __ldg(&w[gene * 3 + 0]);
        const float kk = __ldg(&w[gene * 3 + 1]);
        pn[k] = kk * kk;
    }
    // prod of w2 over all genes (lane owns genes 4*lane+k, k<4, idx<127)
    float w2l = 1.0f;
#pragma unroll
    for (int k = 0; k < 4; ++k) {
        const int idx = 4 * lane + k;
        if (idx < GG) w2l *= __ldg(&w[idx * 3 + 2]);
    }
#pragma unroll
    for (int o = 16; o; o >>= 1)
        w2l *= __shfl_xor_sync(0xFFFFFFFFu, w2l, o);
    const float W2ALL = w2l;

    const float4* __restrict__ xg = reinterpret_cast<const float4*>(x);

    for (int grp = warp; grp < ngroups; grp += nwarps) {
        // ---- 4 aligned vector loads (independent, issued up front) ----
        float4 v[4];
        const size_t base = (size_t)grp * GG;   // float4 units
#pragma unroll
        for (int j = 0; j < 4; ++j) {
            int slot = lane + 32 * j;
            if (slot > 126) slot = 126;          // lane31 j=3: dup, discarded
            v[j] = __ldg(xg + base + slot);
        }

        // ---- low/high split products per slot, folded across rows ----
        float num[4], den[4];
        float hn = 1.0f, hd = 1.0f;              // carry from previous slot
#pragma unroll
        for (int j = 0; j < 4; ++j) {
            const int s = l31 ? (3 - j) : 4;     // split point for this slot
            float ln = 1.0f, ld = 1.0f;          // low part (this row)
            float gn = 1.0f, gd = 1.0f;          // high part (next row)
            const float e[4] = { v[j].x, v[j].y, v[j].z, v[j].w };
#pragma unroll
            for (int c = 0; c < 4; ++c) {
                const int   k  = j + c;
                const float a  = e[c] * e[c];
                const float tn = fmaf(p0[k], a, pn[k]);  // wn + w0*x^2
                const float td = pn[k] + a;              // wn + x^2
                if (c < s) { ln *= tn; ld *= td; }
                else       { gn *= tn; gd *= td; }
            }
            num[j] = hn * ln;
            den[j] = hd * ld;
            hn = gn; hd = gd;
        }

        // ---- 1 division per row (<=4-term operands: safe fp32 range) ----
        float rr[4];
#pragma unroll
        for (int r = 0; r < 4; ++r)
            rr[r] = __fdividef(num[r], den[r]);

        // ---- 32-lane product, 4 independent chains interleaved ----
#pragma unroll
        for (int o = 1; o <= 16; o <<= 1)
#pragma unroll
            for (int r = 0; r < 4; ++r)
                rr[r] *= __shfl_xor_sync(0xFFFFFFFFu, rr[r], o);

        if (lane == 0) {
            float4 o4;
            o4.x = W2ALL * rr[0];
            o4.y = W2ALL * rr[1];
            o4.z = W2ALL * rr[2];
            o4.w = W2ALL * rr[3];
            *reinterpret_cast<float4*>(out + grp * 4) = o4;
        }
    }
}

extern "C" void kernel_launch(void* const* d_in, const int* in_sizes, int n_in,
                              void* d_out, int out_size)
{
    const float* x = (const float*)d_in[0];   // (B, G) fp32
    const float* w = (const float*)d_in[1];   // (G, 3) fp32
    float* out = (float*)d_out;               // (B, 1) fp32

    const int rows    = in_sizes[0] / GG;     // 524288
    const int ngroups = rows / 4;             // 131072

    hill_f4w7_kernel<<<NBLOCKS, NTHREADS>>>(x, w, out, ngroups);
}

// round 16
// speedup vs baseline: 1.0824x; 1.0824x over previous
#include <cuda_runtime.h>
#include <cuda_bf16.h>

// GraphTrainNN: out[b] = prod_g  w2[g] * (w1[g]^2 + w0[g]*x[b,g]^2) / (w1[g]^2 + x[b,g]^2)
// B = 524288 rows, G = 127 genes. x: (B,G) fp32, w: (G,3) fp32.
//
// FINAL (= R14, best measured: 44.38us kernel, DRAM 77.3%, 6.13 TB/s):
// single-wave persistent grid + aligned float4 streaming + low/high
// split-product fold. Everything else in the 15-round search measured slower:
//  - register ping-pong pipelines spill (64-reg cap) or collapse occupancy
//    (90 regs unconstrained); intra-iteration x2 batching costs 10 regs;
//    cp.async smem staging adds instruction overhead; 192-thread blocks or
//    launch-bounds squeezes below 48 regs break the load schedule.
// Design:
//  - 740 blocks = 148 SMs x 5 resident -> exactly one wave, no wave
//    quantization; grid-stride, each warp does 22-23 groups.
//  - 4-row group = 508 floats = 127 float4; warp loads slots lane+32j ->
//    4 aligned LDG.128, 512B contiguous per request (minimum sectors).
//  - gene of element (slot,c) = (4*lane + j + c) mod 127 [128 == 1 mod 127]
//    -> 7 fixed (w0, w1^2) pairs per lane, loaded once per warp.
//  - lane 31 handles row straddles via split points s={3,2,1,0}; others s=4.
//  - 1 fast division per row (operands are <=4-term products: safe fp32
//    range), 5-level butterfly with 4 interleaved chains, float4 store.
//  - prod(w2) over all genes hoisted to a per-warp constant (underflow
//    behavior matches the fp32 reference product exactly; rel_err = 0).

#define GG 127
#define NBLOCKS 740   // 148 SMs x 5 resident blocks: exactly one wave

__global__ __launch_bounds__(256, 5)
void hill_f4w_kernel(const float* __restrict__ x,
                     const float* __restrict__ w,
                     float* __restrict__ out,
                     int ngroups)
{
    const int lane   = threadIdx.x & 31;
    const int warp   = (blockIdx.x * blockDim.x + threadIdx.x) >> 5;
    const int nwarps = (gridDim.x * blockDim.x) >> 5;
    const bool l31   = (lane == 31);

    // ---- per-lane params: genes (4*lane + k) mod 127, k = 0..6 ----
    float p0[7], pn[7];
#pragma unroll
    for (int k = 0; k < 7; ++k) {
        int gene = 4 * lane + k;
        if (gene >= GG) gene -= GG;
        p0[k] = __ldg(&w[gene * 3 + 0]);
        const float kk = __ldg(&w[gene * 3 + 1]);
        pn[k] = kk * kk;
    }
    // prod of w2 over all genes (lane owns genes 4*lane+k, k<4, idx<127)
    float w2l = 1.0f;
#pragma unroll
    for (int k = 0; k < 4; ++k) {
        const int idx = 4 * lane + k;
        if (idx < GG) w2l *= __ldg(&w[idx * 3 + 2]);
    }
#pragma unroll
    for (int o = 16; o; o >>= 1)
        w2l *= __shfl_xor_sync(0xFFFFFFFFu, w2l, o);
    const float W2ALL = w2l;

    const float4* __restrict__ xg = reinterpret_cast<const float4*>(x);

    for (int grp = warp; grp < ngroups; grp += nwarps) {
        // ---- 4 aligned vector loads (independent, issued up front) ----
        float4 v[4];
        const size_t base = (size_t)grp * GG;   // float4 units
#pragma unroll
        for (int j = 0; j < 4; ++j) {
            int slot = lane + 32 * j;
            if (slot > 126) slot = 126;          // lane31 j=3: dup, discarded
            v[j] = __ldg(xg + base + slot);
        }

        // ---- low/high split products per slot, folded across rows ----
        float num[4], den[4];
        float hn = 1.0f, hd = 1.0f;              // carry from previous slot
#pragma unroll
        for (int j = 0; j < 4; ++j) {
            const int s = l31 ? (3 - j) : 4;     // split point for this slot
            float ln = 1.0f, ld = 1.0f;          // low part (this row)
            float gn = 1.0f, gd = 1.0f;          // high part (next row)
            const float e[4] = { v[j].x, v[j].y, v[j].z, v[j].w };
#pragma unroll
            for (int c = 0; c < 4; ++c) {
                const int   k  = j + c;
                const float a  = e[c] * e[c];
                const float tn = fmaf(p0[k], a, pn[k]);  // wn + w0*x^2
                const float td = pn[k] + a;              // wn + x^2
                if (c < s) { ln *= tn; ld *= td; }
                else       { gn *= tn; gd *= td; }
            }
            num[j] = hn * ln;
            den[j] = hd * ld;
            hn = gn; hd = gd;
        }

        // ---- 1 division per row (<=4-term operands: safe fp32 range) ----
        float rr[4];
#pragma unroll
        for (int r = 0; r < 4; ++r)
            rr[r] = __fdividef(num[r], den[r]);

        // ---- 32-lane product, 4 independent chains interleaved ----
#pragma unroll
        for (int o = 1; o <= 16; o <<= 1)
#pragma unroll
            for (int r = 0; r < 4; ++r)
                rr[r] *= __shfl_xor_sync(0xFFFFFFFFu, rr[r], o);

        if (lane == 0) {
            float4 o4;
            o4.x = W2ALL * rr[0];
            o4.y = W2ALL * rr[1];
            o4.z = W2ALL * rr[2];
            o4.w = W2ALL * rr[3];
            *reinterpret_cast<float4*>(out + grp * 4) = o4;
        }
    }
}

extern "C" void kernel_launch(void* const* d_in, const int* in_sizes, int n_in,
                              void* d_out, int out_size)
{
    const float* x = (const float*)d_in[0];   // (B, G) fp32
    const float* w = (const float*)d_in[1];   // (G, 3) fp32
    float* out = (float*)d_out;               // (B, 1) fp32

    const int rows    = in_sizes[0] / GG;     // 524288
    const int ngroups = rows / 4;             // 131072

    hill_f4w_kernel<<<NBLOCKS, 256>>>(x, w, out, ngroups);
}

// round 17
// speedup vs baseline: 1.1250x; 1.0393x over previous
#include <cuda_runtime.h>
#include <cuda_bf16.h>

// GraphTrainNN: out[b] = prod_g  w2[g] * (w1[g]^2 + w0[g]*x[b,g]^2) / (w1[g]^2 + x[b,g]^2)
// B = 524288 rows, G = 127 genes. x: (B,G) fp32, w: (G,3) fp32.
//
// R17 = R14 (best: single-wave persistent grid, aligned float4 streaming,
// low/high split-product fold, 48 regs, 44.4us kernel @ 77% DRAM) with a
// CHEAPER WARP REDUCTION:
//  - old: 5 butterfly levels x 4 chains = 20 SHFL per group.
//  - new: 3 levels x 4 chains (12 SHFL) -> each 8-lane subgroup holds all 4
//    partial products; lane selects chain (lane>>3) with 2 selects; 2 final
//    levels on one value (2 SHFL). Total 14 SHFL (-30% tail latency).
//  - lanes 0/8/16/24 store rows 0..3 as 4 coalesced STG.32 (one sector).
// Memory path (the binding resource) is untouched:
//  - 740 blocks = 148 SMs x 5 resident -> exactly one wave.
//  - 4-row group = 127 float4; 4 aligned LDG.128 per warp, 512B contiguous.
//  - gene of element (slot,c) = (4*lane + j + c) mod 127 -> 7 param pairs/lane.
//  - lane 31 handles row straddles via split points s={3,2,1,0}; others s=4.
//  - 1 fast division per row; prod(w2) hoisted per warp.

#define GG 127
#define NBLOCKS 740   // 148 SMs x 5 resident blocks: exactly one wave

__global__ __launch_bounds__(256, 5)
void hill_f4r_kernel(const float* __restrict__ x,
                     const float* __restrict__ w,
                     float* __restrict__ out,
                     int ngroups)
{
    const int lane   = threadIdx.x & 31;
    const int warp   = (blockIdx.x * blockDim.x + threadIdx.x) >> 5;
    const int nwarps = (gridDim.x * blockDim.x) >> 5;
    const bool l31   = (lane == 31);

    // ---- per-lane params: genes (4*lane + k) mod 127, k = 0..6 ----
    float p0[7], pn[7];
#pragma unroll
    for (int k = 0; k < 7; ++k) {
        int gene = 4 * lane + k;
        if (gene >= GG) gene -= GG;
        p0[k] = __ldg(&w[gene * 3 + 0]);
        const float kk = __ldg(&w[gene * 3 + 1]);
        pn[k] = kk * kk;
    }
    // prod of w2 over all genes (lane owns genes 4*lane+k, k<4, idx<127)
    float w2l = 1.0f;
#pragma unroll
    for (int k = 0; k < 4; ++k) {
        const int idx = 4 * lane + k;
        if (idx < GG) w2l *= __ldg(&w[idx * 3 + 2]);
    }
#pragma unroll
    for (int o = 16; o; o >>= 1)
        w2l *= __shfl_xor_sync(0xFFFFFFFFu, w2l, o);
    const float W2ALL = w2l;

    // which row this lane's subgroup reduces in the final phase
    const int myrow   = lane >> 3;               // 0..3
    const bool storer = (lane & 7) == 0;         // lanes 0,8,16,24

    const float4* __restrict__ xg = reinterpret_cast<const float4*>(x);

    for (int grp = warp; grp < ngroups; grp += nwarps) {
        // ---- 4 aligned vector loads (independent, issued up front) ----
        float4 v[4];
        const size_t base = (size_t)grp * GG;    // float4 units
#pragma unroll
        for (int j = 0; j < 4; ++j) {
            int slot = lane + 32 * j;
            if (slot > 126) slot = 126;           // lane31 j=3: dup, discarded
            v[j] = __ldg(xg + base + slot);
        }

        // ---- low/high split products per slot, folded across rows ----
        float num[4], den[4];
        float hn = 1.0f, hd = 1.0f;               // carry from previous slot
#pragma unroll
        for (int j = 0; j < 4; ++j) {
            const int s = l31 ? (3 - j) : 4;      // split point for this slot
            float ln = 1.0f, ld = 1.0f;           // low part (this row)
            float gn = 1.0f, gd = 1.0f;           // high part (next row)
            const float e[4] = { v[j].x, v[j].y, v[j].z, v[j].w };
#pragma unroll
            for (int c = 0; c < 4; ++c) {
                const int   k  = j + c;
                const float a  = e[c] * e[c];
                const float tn = fmaf(p0[k], a, pn[k]);  // wn + w0*x^2
                const float td = pn[k] + a;              // wn + x^2
                if (c < s) { ln *= tn; ld *= td; }
                else       { gn *= tn; gd *= td; }
            }
            num[j] = hn * ln;
            den[j] = hd * ld;
            hn = gn; hd = gd;
        }

        // ---- 1 division per row (<=4-term operands: safe fp32 range) ----
        float rr[4];
#pragma unroll
        for (int r = 0; r < 4; ++r)
            rr[r] = __fdividef(num[r], den[r]);

        // ---- reduction: 3 levels x 4 chains, select, 2 levels x 1 ----
#pragma unroll
        for (int o = 1; o <= 4; o <<= 1)
#pragma unroll
            for (int r = 0; r < 4; ++r)
                rr[r] *= __shfl_xor_sync(0xFFFFFFFFu, rr[r], o);

        // each 8-lane subgroup now holds all 4 subgroup-partials;
        // subgroup g finishes row g.
        float vsel = (lane & 16) ? ((lane & 8) ? rr[3] : rr[2])
                                 : ((lane & 8) ? rr[1] : rr[0]);
        vsel *= __shfl_xor_sync(0xFFFFFFFFu, vsel, 8);
        vsel *= __shfl_xor_sync(0xFFFFFFFFu, vsel, 16);

        if (storer)
            out[grp * 4 + myrow] = W2ALL * vsel;  // 4 lanes, one sector
    }
}

extern "C" void kernel_launch(void* const* d_in, const int* in_sizes, int n_in,
                              void* d_out, int out_size)
{
    const float* x = (const float*)d_in[0];   // (B, G) fp32
    const float* w = (const float*)d_in[1];   // (G, 3) fp32
    float* out = (float*)d_out;               // (B, 1) fp32

    const int rows    = in_sizes[0] / GG;     // 524288
    const int ngroups = rows / 4;             // 131072

    hill_f4r_kernel<<<NBLOCKS, 256>>>(x, w, out, ngroups);
}